// round 1
// baseline (speedup 1.0000x reference)
#include <cuda_runtime.h>

// VectorQuantizer: x [B=64, C=64, H=32, W=32] fp32, weight [K=1024, D=64] fp32.
// latents[n, d] = x[b, d, h, w] with n = (b*32 + h)*32 + w  (d-stride = H*W = 1024)
// score_k = ||w_k||^2 - 2 * latent . w_k   (||latent||^2 is argmin-invariant)
// out[n] = weight[argmin_k score_k]   (STE output == quantized up to 1 ulp)

#define D      64
#define K      1024
#define TILE   128
#define NTILES (K / TILE)
#define BLOCK  256
#define HW     1024   // H*W, d-stride inside x

__global__ __launch_bounds__(BLOCK)
void vq_kernel(const float* __restrict__ x,
               const float* __restrict__ w,
               float* __restrict__ out)
{
    __shared__ float s_w[TILE * D];   // 32 KB codebook tile
    __shared__ float s_wn[TILE];      // per-row squared norms
    __shared__ int   s_idx[BLOCK];    // winning index per point

    const int tid = threadIdx.x;
    const int n   = blockIdx.x * BLOCK + tid;   // grid*block == N exactly

    // ---- load this point's latent into registers as -2*x (coalesced per d) ----
    const int b  = n >> 10;          // n / (H*W)
    const int hw = n & (HW - 1);
    const float* xp = x + (size_t)b * D * HW + hw;
    float xm[D];
#pragma unroll
    for (int d = 0; d < D; d++) xm[d] = -2.0f * xp[d * HW];

    float best = 3.402823466e38f;
    int   bidx = 0;

    for (int t = 0; t < NTILES; t++) {
        // ---- cooperative tile load: 128 rows x 64 floats = 8192 floats ----
        {
            const float4* wg  = (const float4*)(w + (size_t)t * TILE * D);
            float4*       sw4 = (float4*)s_w;
#pragma unroll
            for (int i = 0; i < (TILE * D / 4) / BLOCK; i++)   // 8 iters
                sw4[tid + i * BLOCK] = wg[tid + i * BLOCK];
        }
        __syncthreads();

        // ---- per-row squared norms (first TILE threads) ----
        if (tid < TILE) {
            const float* row = s_w + tid * D;
            float s = 0.0f;
#pragma unroll
            for (int d = 0; d < D; d++) s = fmaf(row[d], row[d], s);
            s_wn[tid] = s;
        }
        __syncthreads();

        // ---- score 4 codewords at a time (ILP=4 accumulator chains) ----
        for (int k = 0; k < TILE; k += 4) {
            float a0 = s_wn[k + 0];
            float a1 = s_wn[k + 1];
            float a2 = s_wn[k + 2];
            float a3 = s_wn[k + 3];
            const float4* r0 = (const float4*)(s_w + (k + 0) * D);
            const float4* r1 = (const float4*)(s_w + (k + 1) * D);
            const float4* r2 = (const float4*)(s_w + (k + 2) * D);
            const float4* r3 = (const float4*)(s_w + (k + 3) * D);
#pragma unroll
            for (int q = 0; q < D / 4; q++) {
                float4 w0 = r0[q];
                float4 w1 = r1[q];
                float4 w2 = r2[q];
                float4 w3 = r3[q];
                a0 = fmaf(w0.x, xm[4*q + 0], a0);
                a1 = fmaf(w1.x, xm[4*q + 0], a1);
                a2 = fmaf(w2.x, xm[4*q + 0], a2);
                a3 = fmaf(w3.x, xm[4*q + 0], a3);
                a0 = fmaf(w0.y, xm[4*q + 1], a0);
                a1 = fmaf(w1.y, xm[4*q + 1], a1);
                a2 = fmaf(w2.y, xm[4*q + 1], a2);
                a3 = fmaf(w3.y, xm[4*q + 1], a3);
                a0 = fmaf(w0.z, xm[4*q + 2], a0);
                a1 = fmaf(w1.z, xm[4*q + 2], a1);
                a2 = fmaf(w2.z, xm[4*q + 2], a2);
                a3 = fmaf(w3.z, xm[4*q + 2], a3);
                a0 = fmaf(w0.w, xm[4*q + 3], a0);
                a1 = fmaf(w1.w, xm[4*q + 3], a1);
                a2 = fmaf(w2.w, xm[4*q + 3], a2);
                a3 = fmaf(w3.w, xm[4*q + 3], a3);
            }
            // strict < keeps the earliest index on ties (matches jnp.argmin)
            const int kb = t * TILE + k;
            if (a0 < best) { best = a0; bidx = kb + 0; }
            if (a1 < best) { best = a1; bidx = kb + 1; }
            if (a2 < best) { best = a2; bidx = kb + 2; }
            if (a3 < best) { best = a3; bidx = kb + 3; }
        }
        __syncthreads();   // protect s_w before next tile overwrite
    }

    s_idx[tid] = bidx;
    __syncthreads();

    // ---- coalesced gather + store of the quantized rows ----
    {
        const float4* w4 = (const float4*)w;
        float4*       o4 = (float4*)out;
        const size_t  obase = (size_t)blockIdx.x * BLOCK * (D / 4);
#pragma unroll 4
        for (int i = tid; i < BLOCK * (D / 4); i += BLOCK) {
            const int p  = i >> 4;        // point within block (D/4 == 16)
            const int d4 = i & 15;
            o4[obase + i] = w4[(size_t)s_idx[p] * (D / 4) + d4];
        }
    }
}

extern "C" void kernel_launch(void* const* d_in, const int* in_sizes, int n_in,
                              void* d_out, int out_size)
{
    const float* x = (const float*)d_in[0];   // [64, 64, 32, 32]
    const float* w = (const float*)d_in[1];   // [1024, 64]
    float* out = (float*)d_out;               // [65536, 64]
    (void)in_sizes; (void)n_in; (void)out_size;

    const int n_points = 64 * 32 * 32;        // 65536
    vq_kernel<<<n_points / BLOCK, BLOCK>>>(x, w, out);
}

// round 4
// speedup vs baseline: 1.1824x; 1.1824x over previous
#include <cuda_runtime.h>
#include <cuda_fp16.h>
#include <cstdint>

// VectorQuantizer via classic tensor cores (mma.sync m16n8k16, fp16 in / fp32 acc).
// score_k = ||w_k||^2 + y.w_k with y = -2x; y,w split fp16 hi/lo, 3 MMA passes.
// Per-point top-2 tracked in registers; exact fp32 rerank when gap < 0.02.

#define D      64
#define K      1024
#define MTILE  128        // points per CTA
#define WTILE  256        // codewords per smem tile
#define KT     (K / WTILE)
#define BLOCK  256
#define HW     1024       // d-stride inside x

// ---- smem layout (bytes) ----
#define OFF_YHI 0                 // 128 x 128B fp16
#define OFF_YLO 16384
#define OFF_WHI 32768             // 256 x 128B fp16
#define OFF_WLO 65536
#define OFF_WN  98304             // 1024 fp32 norms
#define OFF_TOP 102400            // 128 x float4 (b1, i1, b2, i2)
#define OFF_IDX 104448            // 128 int
#define SMEM_TOTAL 104960

#define SW(o) ((o) ^ (((o) >> 3) & 0x70))

static __device__ __forceinline__ uint32_t smem_u32(const void* p) {
    uint32_t a;
    asm("{ .reg .u64 t; cvta.to.shared.u64 t, %1; cvt.u32.u64 %0, t; }" : "=r"(a) : "l"(p));
    return a;
}

static __device__ __forceinline__ void ldsm4(uint32_t r[4], uint32_t addr) {
    asm volatile("ldmatrix.sync.aligned.m8n8.x4.shared.b16 {%0,%1,%2,%3}, [%4];"
                 : "=r"(r[0]), "=r"(r[1]), "=r"(r[2]), "=r"(r[3]) : "r"(addr));
}

static __device__ __forceinline__ void mma16816(float c[4], const uint32_t a[4],
                                                uint32_t b0, uint32_t b1) {
    asm volatile("mma.sync.aligned.m16n8k16.row.col.f32.f16.f16.f32 "
                 "{%0,%1,%2,%3}, {%4,%5,%6,%7}, {%8,%9}, {%0,%1,%2,%3};"
                 : "+f"(c[0]), "+f"(c[1]), "+f"(c[2]), "+f"(c[3])
                 : "r"(a[0]), "r"(a[1]), "r"(a[2]), "r"(a[3]), "r"(b0), "r"(b1));
}

static __device__ __forceinline__ void top2_upd(float& b1, int& i1, float& b2, int& i2,
                                                float v, int c) {
    if (v < b1)      { b2 = b1; i2 = i1; b1 = v; i1 = c; }
    else if (v < b2) { b2 = v; i2 = c; }
}

static __device__ __forceinline__ void top2_merge(float& b1, int& i1, float& b2, int& i2,
                                                  float o1, int oi1, float o2, int oi2) {
    bool lt1 = (o1 < b1) || (o1 == b1 && oi1 < i1);
    if (lt1) {
        bool keep = (b1 < o2) || (b1 == o2 && i1 < oi2);
        if (keep) { b2 = b1; i2 = i1; } else { b2 = o2; i2 = oi2; }
        b1 = o1; i1 = oi1;
    } else {
        if ((o1 < b2) || (o1 == b2 && oi1 < i2)) { b2 = o1; i2 = oi1; }
    }
}

__global__ __launch_bounds__(BLOCK, 2)
void vq_hmma_kernel(const float* __restrict__ x,
                    const float* __restrict__ w,
                    float* __restrict__ out)
{
    extern __shared__ char sm[];
    const uint32_t smb = smem_u32(sm);
    const int tid  = threadIdx.x;
    const int lane = tid & 31;
    const int warp = tid >> 5;

    const int n0   = blockIdx.x * MTILE;
    const int bimg = n0 >> 10;
    const int hw0  = n0 & (HW - 1);

    // ---- build Y = -2x, split fp16 hi/lo, SW128 swizzled [128 pts][64 halfs] ----
    {
        const int p  = tid & 127;
        const int d0 = (tid >> 7) * 32;
        const float* xp = x + (size_t)bimg * D * HW + hw0 + p;
        char* yhi = sm + OFF_YHI;
        char* ylo = sm + OFF_YLO;
        const uint32_t rb = (uint32_t)p * 128;
#pragma unroll
        for (int dd = 0; dd < 32; dd += 2) {
            const int d = d0 + dd;
            float v0 = -2.0f * xp[(size_t)d * HW];
            float v1 = -2.0f * xp[(size_t)(d + 1) * HW];
            __half h0 = __float2half_rn(v0), h1 = __float2half_rn(v1);
            __half l0 = __float2half_rn(v0 - __half2float(h0));
            __half l1 = __float2half_rn(v1 - __half2float(h1));
            uint32_t o = SW(rb + (uint32_t)d * 2);
            *(__half2*)(yhi + o) = __halves2half2(h0, h1);
            *(__half2*)(ylo + o) = __halves2half2(l0, l1);
        }
    }

    // ---- codeword squared norms (fp32) ----
    {
        float* wn = (float*)(sm + OFF_WN);
#pragma unroll
        for (int r = 0; r < K / BLOCK; r++) {
            const int k = tid + r * BLOCK;
            const float4* wr = (const float4*)(w + (size_t)k * D);
            float s = 0.0f;
#pragma unroll
            for (int q = 0; q < D / 4; q++) {
                float4 f = wr[q];
                s = fmaf(f.x, f.x, s); s = fmaf(f.y, f.y, s);
                s = fmaf(f.z, f.z, s); s = fmaf(f.w, f.w, s);
            }
            wn[k] = s;
        }
    }
    __syncthreads();

    // ---- A fragments (this warp's 16 points x 64 d), hi and lo, kept in regs ----
    uint32_t ahi[4][4], alo[4][4];
    const int lr = lane & 7;
    const int mI = lane >> 3;
    {
        const uint32_t arow = (uint32_t)(warp * 16 + (mI & 1) * 8 + lr) * 128;
#pragma unroll
        for (int kc = 0; kc < 4; kc++) {
            uint32_t ch = (uint32_t)((kc * 2 + (mI >> 1)) ^ lr) * 16;
            ldsm4(ahi[kc], smb + OFF_YHI + arow + ch);
            ldsm4(alo[kc], smb + OFF_YLO + arow + ch);
        }
    }

    const uint32_t offb0 = (uint32_t)lr * 128 + (uint32_t)(mI ^ lr) * 16;       // chunks 0-3
    const uint32_t offb1 = (uint32_t)lr * 128 + (uint32_t)((4 + mI) ^ lr) * 16; // chunks 4-7
    const float* wn = (const float*)(sm + OFF_WN);

    float bA1 = 3.402823466e38f, bA2 = 3.402823466e38f;
    float bB1 = 3.402823466e38f, bB2 = 3.402823466e38f;
    int iA1 = 0, iA2 = 0, iB1 = 0, iB2 = 0;

#pragma unroll 1
    for (int kt = 0; kt < KT; kt++) {
        __syncthreads();   // previous tile fully consumed
        // ---- convert W tile (256 codewords) fp32 -> fp16 hi/lo, swizzled ----
        {
            const float2* wt = (const float2*)(w + (size_t)kt * WTILE * D);
            char* whi = sm + OFF_WHI;
            char* wlo = sm + OFF_WLO;
#pragma unroll
            for (int it = 0; it < (WTILE * D / 2) / BLOCK; it++) {   // 32
                const int i  = tid + it * BLOCK;
                float2 v = wt[i];
                const int pr = i >> 5;
                const int pc = (i & 31) * 2;
                __half h0 = __float2half_rn(v.x), h1 = __float2half_rn(v.y);
                __half l0 = __float2half_rn(v.x - __half2float(h0));
                __half l1 = __float2half_rn(v.y - __half2float(h1));
                uint32_t o = SW((uint32_t)(pr * 128 + pc * 2));
                *(__half2*)(whi + o) = __halves2half2(h0, h1);
                *(__half2*)(wlo + o) = __halves2half2(l0, l1);
            }
        }
        __syncthreads();

        // ---- sweep the tile in 32-codeword groups (4 independent m16n8 chains) ----
#pragma unroll 1
        for (int g = 0; g < WTILE / 32; g++) {
            const uint32_t gbhi = smb + OFF_WHI + (uint32_t)g * 32 * 128;
            const uint32_t gblo = smb + OFF_WLO + (uint32_t)g * 32 * 128;
            float c[4][4];
#pragma unroll
            for (int nt = 0; nt < 4; nt++)
#pragma unroll
                for (int q = 0; q < 4; q++) c[nt][q] = 0.0f;

            // pass group 1: B = hi, A in {hi, lo}
#pragma unroll
            for (int kc32 = 0; kc32 < 2; kc32++) {
                const uint32_t ob = kc32 ? offb1 : offb0;
#pragma unroll
                for (int nt = 0; nt < 4; nt++) {
                    uint32_t bb[4];
                    ldsm4(bb, gbhi + (uint32_t)nt * 1024 + ob);
                    mma16816(c[nt], ahi[kc32 * 2],     bb[0], bb[1]);
                    mma16816(c[nt], ahi[kc32 * 2 + 1], bb[2], bb[3]);
                    mma16816(c[nt], alo[kc32 * 2],     bb[0], bb[1]);
                    mma16816(c[nt], alo[kc32 * 2 + 1], bb[2], bb[3]);
                }
            }
            // pass group 2: B = lo, A = hi
#pragma unroll
            for (int kc32 = 0; kc32 < 2; kc32++) {
                const uint32_t ob = kc32 ? offb1 : offb0;
#pragma unroll
                for (int nt = 0; nt < 4; nt++) {
                    uint32_t bb[4];
                    ldsm4(bb, gblo + (uint32_t)nt * 1024 + ob);
                    mma16816(c[nt], ahi[kc32 * 2],     bb[0], bb[1]);
                    mma16816(c[nt], ahi[kc32 * 2 + 1], bb[2], bb[3]);
                }
            }

            // ---- epilogue: add norms, update per-row top-2 ----
            const int colb = kt * WTILE + g * 32 + 2 * (lane & 3);
#pragma unroll
            for (int nt = 0; nt < 4; nt++) {
                const int c0 = colb + nt * 8;
                const float nn0 = wn[c0], nn1 = wn[c0 + 1];
                top2_upd(bA1, iA1, bA2, iA2, c[nt][0] + nn0, c0);
                top2_upd(bA1, iA1, bA2, iA2, c[nt][1] + nn1, c0 + 1);
                top2_upd(bB1, iB1, bB2, iB2, c[nt][2] + nn0, c0);
                top2_upd(bB1, iB1, bB2, iB2, c[nt][3] + nn1, c0 + 1);
            }
        }
    }

    // ---- merge top-2 across the 4 lanes sharing each row ----
#pragma unroll
    for (int mm = 1; mm <= 2; mm <<= 1) {
        float o1, o2; int oi1, oi2;
        o1 = __shfl_xor_sync(0xFFFFFFFFu, bA1, mm); oi1 = __shfl_xor_sync(0xFFFFFFFFu, iA1, mm);
        o2 = __shfl_xor_sync(0xFFFFFFFFu, bA2, mm); oi2 = __shfl_xor_sync(0xFFFFFFFFu, iA2, mm);
        top2_merge(bA1, iA1, bA2, iA2, o1, oi1, o2, oi2);
        o1 = __shfl_xor_sync(0xFFFFFFFFu, bB1, mm); oi1 = __shfl_xor_sync(0xFFFFFFFFu, iB1, mm);
        o2 = __shfl_xor_sync(0xFFFFFFFFu, bB2, mm); oi2 = __shfl_xor_sync(0xFFFFFFFFu, iB2, mm);
        top2_merge(bB1, iB1, bB2, iB2, o1, oi1, o2, oi2);
    }
    if ((lane & 3) == 0) {
        float4* top = (float4*)(sm + OFF_TOP);
        const int pA = warp * 16 + (lane >> 2);
        top[pA]     = make_float4(bA1, __int_as_float(iA1), bA2, __int_as_float(iA2));
        top[pA + 8] = make_float4(bB1, __int_as_float(iB1), bB2, __int_as_float(iB2));
    }
    __syncthreads();

    // ---- exact fp32 rerank of top-2 when the approx gap is small ----
    int* sidx = (int*)(sm + OFF_IDX);
    if (tid < MTILE) {
        float4 t = ((const float4*)(sm + OFF_TOP))[tid];
        int i1 = __float_as_int(t.y), i2 = __float_as_int(t.w);
        int fi = i1;
        if (t.z - t.x < 0.02f && i2 != i1) {
            const float* xr = x + (size_t)bimg * D * HW + hw0 + tid;
            const float* w1 = w + (size_t)i1 * D;
            const float* w2 = w + (size_t)i2 * D;
            float s1 = 0.0f, s2 = 0.0f;
#pragma unroll 8
            for (int d = 0; d < D; d++) {
                float xv = xr[(size_t)d * HW];
                float a = w1[d], cc = w2[d];
                s1 = fmaf(a,  fmaf(-2.0f, xv, a),  s1);
                s2 = fmaf(cc, fmaf(-2.0f, xv, cc), s2);
            }
            if (s2 < s1 || (s2 == s1 && i2 < i1)) fi = i2;
        }
        sidx[tid] = fi;
    }
    __syncthreads();

    // ---- coalesced gather of winning codewords ----
    {
        const float4* w4 = (const float4*)w;
        float4* o4 = (float4*)out;
        const size_t obase = (size_t)blockIdx.x * MTILE * (D / 4);
#pragma unroll 4
        for (int i = tid; i < MTILE * (D / 4); i += BLOCK) {
            const int p = i >> 4, d4 = i & 15;
            o4[obase + i] = w4[(size_t)sidx[p] * (D / 4) + d4];
        }
    }
}

extern "C" void kernel_launch(void* const* d_in, const int* in_sizes, int n_in,
                              void* d_out, int out_size)
{
    const float* x = (const float*)d_in[0];   // [64, 64, 32, 32]
    const float* w = (const float*)d_in[1];   // [1024, 64]
    float* out = (float*)d_out;               // [65536, 64]
    (void)in_sizes; (void)n_in; (void)out_size;

    cudaFuncSetAttribute(vq_hmma_kernel, cudaFuncAttributeMaxDynamicSharedMemorySize, SMEM_TOTAL);
    vq_hmma_kernel<<<65536 / MTILE, BLOCK, SMEM_TOTAL>>>(x, w, out);
}

// round 5
// speedup vs baseline: 2.7109x; 2.2928x over previous
#include <cuda_runtime.h>
#include <cuda_fp16.h>
#include <cstdint>

// VectorQuantizer via mma.sync m16n8k16 (fp16 in / fp32 acc), fp16 hi/lo split
// (3 passes). Codebook pre-converted once (pre-kernel) into swizzled global
// scratch; main kernel streams tiles via cp.async. Branchless packed-key top-2
// epilogue with accumulators initialized to ||w||^2; exact fp32 rerank of top-2.

#define D      64
#define K      1024
#define MTILE  256        // points per CTA
#define WTILE  256        // codewords per tile
#define KT     (K / WTILE)
#define BLOCK  512
#define HW     1024       // d-stride inside x

// ---- smem layout (bytes) ----
#define OFF_YHI 0                 // 256 x 128B fp16
#define OFF_YLO 32768
#define OFF_W   65536             // 2 buffers x (hi 32KB + lo 32KB)
#define W_BUF   65536
#define OFF_WN  196608            // 1024 fp32 norms
#define OFF_TOP 200704            // 256 x uint2 (k1, k2)
#define OFF_IDX 202752            // 256 int
#define SMEM_TOTAL 203776

#define SW(o) ((o) ^ (((o) >> 3) & 0x70))

// ---- global scratch: swizzled fp16 codebook tiles (hi,lo) + norms ----
__device__ __align__(1024) static char  g_wsw[KT][2][WTILE * 128];
__device__ __align__(16)   static float g_wn[K];

static __device__ __forceinline__ uint32_t smem_u32(const void* p) {
    uint32_t a;
    asm("{ .reg .u64 t; cvta.to.shared.u64 t, %1; cvt.u32.u64 %0, t; }" : "=r"(a) : "l"(p));
    return a;
}
static __device__ __forceinline__ void cp16(uint32_t saddr, const void* g) {
    asm volatile("cp.async.cg.shared.global [%0], [%1], 16;"
                 :: "r"(saddr), "l"((size_t)__cvta_generic_to_global(g)) : "memory");
}
static __device__ __forceinline__ void ldsm4(uint32_t r[4], uint32_t addr) {
    asm volatile("ldmatrix.sync.aligned.m8n8.x4.shared.b16 {%0,%1,%2,%3}, [%4];"
                 : "=r"(r[0]), "=r"(r[1]), "=r"(r[2]), "=r"(r[3]) : "r"(addr));
}
static __device__ __forceinline__ void mma16816(float c[4], const uint32_t a[4],
                                                uint32_t b0, uint32_t b1) {
    asm volatile("mma.sync.aligned.m16n8k16.row.col.f32.f16.f16.f32 "
                 "{%0,%1,%2,%3}, {%4,%5,%6,%7}, {%8,%9}, {%0,%1,%2,%3};"
                 : "+f"(c[0]), "+f"(c[1]), "+f"(c[2]), "+f"(c[3])
                 : "r"(a[0]), "r"(a[1]), "r"(a[2]), "r"(a[3]), "r"(b0), "r"(b1));
}
static __device__ __forceinline__ uint32_t umn(uint32_t a, uint32_t b) { return a < b ? a : b; }
static __device__ __forceinline__ uint32_t umx(uint32_t a, uint32_t b) { return a > b ? a : b; }

// order-preserving float -> u32, index packed in low 10 bits
static __device__ __forceinline__ void key_upd(uint32_t& k1, uint32_t& k2, float v, int col) {
    uint32_t u = __float_as_uint(v);
    u ^= (uint32_t)((int)u >> 31) | 0x80000000u;
    uint32_t key = (u & 0xFFFFFC00u) | (uint32_t)col;
    uint32_t mn = umn(k1, key);
    k2 = umn(k2, umx(k1, key));
    k1 = mn;
}

// ---------------- pre-kernel: convert codebook once ----------------
__global__ __launch_bounds__(256)
void vq_prep_kernel(const float* __restrict__ w)
{
    const int gid = blockIdx.x * 256 + threadIdx.x;   // 64 blocks -> 16384 threads
#pragma unroll
    for (int r = 0; r < 2; r++) {
        const int i  = gid + r * 16384;               // pair index, 32768 total
        const int kr = i >> 5;                        // codeword 0..1023
        const int p  = i & 31;                        // pair within row
        float2 v = ((const float2*)w)[i];
        __half h0 = __float2half_rn(v.x), h1 = __float2half_rn(v.y);
        __half l0 = __float2half_rn(v.x - __half2float(h0));
        __half l1 = __float2half_rn(v.y - __half2float(h1));
        const int kt = kr >> 8, pr = kr & 255;
        uint32_t o = SW((uint32_t)(pr * 128 + p * 4));
        *(__half2*)(g_wsw[kt][0] + o) = __halves2half2(h0, h1);
        *(__half2*)(g_wsw[kt][1] + o) = __halves2half2(l0, l1);
    }
    if (gid < K) {
        const float4* wr = (const float4*)(w + (size_t)gid * D);
        float s = 0.0f;
#pragma unroll
        for (int q = 0; q < D / 4; q++) {
            float4 f = wr[q];
            s = fmaf(f.x, f.x, s); s = fmaf(f.y, f.y, s);
            s = fmaf(f.z, f.z, s); s = fmaf(f.w, f.w, s);
        }
        g_wn[gid] = s;
    }
}

// ---------------- main kernel ----------------
__global__ __launch_bounds__(BLOCK, 1)
void vq_hmma_kernel(const float* __restrict__ x,
                    const float* __restrict__ w,
                    float* __restrict__ out)
{
    extern __shared__ char sm[];
    const uint32_t smb = smem_u32(sm);
    const int tid  = threadIdx.x;
    const int lane = tid & 31;
    const int warp = tid >> 5;

    const int n0   = blockIdx.x * MTILE;
    const int bimg = n0 >> 10;
    const int hw0  = n0 & (HW - 1);

    // ---- prefetch: norms + tile0 (group 0), tile1 (group 1) ----
    if (tid < 256) cp16(smb + OFF_WN + tid * 16, g_wn + tid * 4);
    {
        uint32_t dst = smb + OFF_W;                     // buf 0
        const char* src = g_wsw[0][0];
#pragma unroll
        for (int i = 0; i < 8; i++) {
            int off = (tid + i * BLOCK) * 16;
            cp16(dst + off, src + off);
        }
    }
    asm volatile("cp.async.commit_group;" ::: "memory");
    {
        uint32_t dst = smb + OFF_W + W_BUF;             // buf 1
        const char* src = g_wsw[1][0];
#pragma unroll
        for (int i = 0; i < 8; i++) {
            int off = (tid + i * BLOCK) * 16;
            cp16(dst + off, src + off);
        }
    }
    asm volatile("cp.async.commit_group;" ::: "memory");

    // ---- build Y = -2x, fp16 hi/lo, swizzled [256 pts][64 halfs] ----
    {
        const int p  = tid & 255;
        const int d0 = (tid >> 8) * 32;
        const float* xp = x + (size_t)bimg * D * HW + hw0 + p;
        char* yhi = sm + OFF_YHI;
        char* ylo = sm + OFF_YLO;
        const uint32_t rb = (uint32_t)p * 128;
#pragma unroll
        for (int dd = 0; dd < 32; dd += 2) {
            const int d = d0 + dd;
            float v0 = -2.0f * xp[(size_t)d * HW];
            float v1 = -2.0f * xp[(size_t)(d + 1) * HW];
            __half h0 = __float2half_rn(v0), h1 = __float2half_rn(v1);
            __half l0 = __float2half_rn(v0 - __half2float(h0));
            __half l1 = __float2half_rn(v1 - __half2float(h1));
            uint32_t o = SW(rb + (uint32_t)d * 2);
            *(__half2*)(yhi + o) = __halves2half2(h0, h1);
            *(__half2*)(ylo + o) = __halves2half2(l0, l1);
        }
    }
    __syncthreads();   // Y visible to ldmatrix

    // ---- A fragments (this warp's 16 points x 64 d), hi and lo, in regs ----
    uint32_t ahi[4][4], alo[4][4];
    const int lr = lane & 7;
    const int mI = lane >> 3;
    {
        const uint32_t arow = (uint32_t)(warp * 16 + (mI & 1) * 8 + lr) * 128;
#pragma unroll
        for (int kc = 0; kc < 4; kc++) {
            uint32_t ch = (uint32_t)((kc * 2 + (mI >> 1)) ^ lr) * 16;
            ldsm4(ahi[kc], smb + OFF_YHI + arow + ch);
            ldsm4(alo[kc], smb + OFF_YLO + arow + ch);
        }
    }

    const uint32_t offb0 = (uint32_t)lr * 128 + (uint32_t)(mI ^ lr) * 16;       // k-chunks 0-3
    const uint32_t offb1 = (uint32_t)lr * 128 + (uint32_t)((4 + mI) ^ lr) * 16; // k-chunks 4-7
    const float* wn = (const float*)(sm + OFF_WN);

    uint32_t kA1 = 0xFFFFFFFFu, kA2 = 0xFFFFFFFFu;
    uint32_t kB1 = 0xFFFFFFFFu, kB2 = 0xFFFFFFFFu;

#pragma unroll 1
    for (int kt = 0; kt < KT; kt++) {
        const int buf = kt & 1;
        if (kt < KT - 1) asm volatile("cp.async.wait_group 1;" ::: "memory");
        else             asm volatile("cp.async.wait_group 0;" ::: "memory");
        __syncthreads();   // tile visible to all warps; prior compute on buf done

        const uint32_t gbhi = smb + OFF_W + (uint32_t)buf * W_BUF;
        const uint32_t gblo = gbhi + 32768;

#pragma unroll 1
        for (int g = 0; g < WTILE / 32; g++) {
            const uint32_t th = gbhi + (uint32_t)g * 32 * 128;
            const uint32_t tl = gblo + (uint32_t)g * 32 * 128;
            const int colb = kt * WTILE + g * 32 + 2 * (lane & 3);

            float c[4][4];
#pragma unroll
            for (int nt = 0; nt < 4; nt++) {
                float2 nn = *(const float2*)(wn + colb + nt * 8);
                c[nt][0] = nn.x; c[nt][1] = nn.y;
                c[nt][2] = nn.x; c[nt][3] = nn.y;
            }

            // pass group 1: B = hi, A in {hi, lo}
#pragma unroll
            for (int kc32 = 0; kc32 < 2; kc32++) {
                const uint32_t ob = kc32 ? offb1 : offb0;
#pragma unroll
                for (int nt = 0; nt < 4; nt++) {
                    uint32_t bb[4];
                    ldsm4(bb, th + (uint32_t)nt * 1024 + ob);
                    mma16816(c[nt], ahi[kc32 * 2],     bb[0], bb[1]);
                    mma16816(c[nt], ahi[kc32 * 2 + 1], bb[2], bb[3]);
                    mma16816(c[nt], alo[kc32 * 2],     bb[0], bb[1]);
                    mma16816(c[nt], alo[kc32 * 2 + 1], bb[2], bb[3]);
                }
            }
            // pass group 2: B = lo, A = hi
#pragma unroll
            for (int kc32 = 0; kc32 < 2; kc32++) {
                const uint32_t ob = kc32 ? offb1 : offb0;
#pragma unroll
                for (int nt = 0; nt < 4; nt++) {
                    uint32_t bb[4];
                    ldsm4(bb, tl + (uint32_t)nt * 1024 + ob);
                    mma16816(c[nt], ahi[kc32 * 2],     bb[0], bb[1]);
                    mma16816(c[nt], ahi[kc32 * 2 + 1], bb[2], bb[3]);
                }
            }

            // ---- branchless packed-key top-2 ----
#pragma unroll
            for (int nt = 0; nt < 4; nt++) {
                const int c0 = colb + nt * 8;
                key_upd(kA1, kA2, c[nt][0], c0);
                key_upd(kA1, kA2, c[nt][1], c0 + 1);
                key_upd(kB1, kB2, c[nt][2], c0);
                key_upd(kB1, kB2, c[nt][3], c0 + 1);
            }
        }
        __syncthreads();   // compute on buf done -> safe to overwrite
        if (kt + 2 < KT) {
            uint32_t dst = smb + OFF_W + (uint32_t)buf * W_BUF;
            const char* src = g_wsw[kt + 2][0];
#pragma unroll
            for (int i = 0; i < 8; i++) {
                int off = (tid + i * BLOCK) * 16;
                cp16(dst + off, src + off);
            }
            asm volatile("cp.async.commit_group;" ::: "memory");
        }
    }

    // ---- merge top-2 across the 4 lanes sharing each row ----
#pragma unroll
    for (int mm = 1; mm <= 2; mm <<= 1) {
        uint32_t o1, o2, mn;
        o1 = __shfl_xor_sync(0xFFFFFFFFu, kA1, mm);
        o2 = __shfl_xor_sync(0xFFFFFFFFu, kA2, mm);
        mn = umn(kA1, o1); kA2 = umn(umn(kA2, o2), umx(kA1, o1)); kA1 = mn;
        o1 = __shfl_xor_sync(0xFFFFFFFFu, kB1, mm);
        o2 = __shfl_xor_sync(0xFFFFFFFFu, kB2, mm);
        mn = umn(kB1, o1); kB2 = umn(umn(kB2, o2), umx(kB1, o1)); kB1 = mn;
    }
    if ((lane & 3) == 0) {
        uint2* top = (uint2*)(sm + OFF_TOP);
        const int pA = warp * 16 + (lane >> 2);
        top[pA]     = make_uint2(kA1, kA2);
        top[pA + 8] = make_uint2(kB1, kB2);
    }
    __syncthreads();

    // ---- exact fp32 rerank of the two candidates (always) ----
    int* sidx = (int*)(sm + OFF_IDX);
    if (tid < MTILE) {
        uint2 t = ((const uint2*)(sm + OFF_TOP))[tid];
        int i1 = (int)(t.x & 1023u), i2 = (int)(t.y & 1023u);
        int fi = i1;
        if (i2 != i1) {
            const float* xr = x + (size_t)bimg * D * HW + hw0 + tid;
            const float* w1 = w + (size_t)i1 * D;
            const float* w2 = w + (size_t)i2 * D;
            float s1 = 0.0f, s2 = 0.0f;
#pragma unroll 8
            for (int d = 0; d < D; d++) {
                float xv = xr[(size_t)d * HW];
                float a = w1[d], cc = w2[d];
                s1 = fmaf(a,  fmaf(-2.0f, xv, a),  s1);
                s2 = fmaf(cc, fmaf(-2.0f, xv, cc), s2);
            }
            if (s2 < s1 || (s2 == s1 && i2 < i1)) fi = i2;
        }
        sidx[tid] = fi;
    }
    __syncthreads();

    // ---- coalesced gather of winning codewords ----
    {
        const float4* w4 = (const float4*)w;
        float4* o4 = (float4*)out;
        const size_t obase = (size_t)blockIdx.x * MTILE * (D / 4);
#pragma unroll 4
        for (int i = tid; i < MTILE * (D / 4); i += BLOCK) {
            const int p = i >> 4, d4 = i & 15;
            o4[obase + i] = w4[(size_t)sidx[p] * (D / 4) + d4];
        }
    }
}

extern "C" void kernel_launch(void* const* d_in, const int* in_sizes, int n_in,
                              void* d_out, int out_size)
{
    const float* x = (const float*)d_in[0];   // [64, 64, 32, 32]
    const float* w = (const float*)d_in[1];   // [1024, 64]
    float* out = (float*)d_out;               // [65536, 64]
    (void)in_sizes; (void)n_in; (void)out_size;

    vq_prep_kernel<<<64, 256>>>(w);
    cudaFuncSetAttribute(vq_hmma_kernel, cudaFuncAttributeMaxDynamicSharedMemorySize, SMEM_TOTAL);
    vq_hmma_kernel<<<65536 / MTILE, BLOCK, SMEM_TOTAL>>>(x, w, out);
}

// round 6
// speedup vs baseline: 2.7637x; 1.0195x over previous
#include <cuda_runtime.h>
#include <cuda_fp16.h>
#include <cstdint>

// VectorQuantizer via mma.sync m16n8k16 (fp16 in / fp32 acc), fp16 hi/lo split
// (3 passes). Codebook pre-converted once into swizzled global scratch; tiles
// streamed via cp.async. Accumulators init to ||w||^2+||x||^2+1 (scores >= ~1,
// u32-comparable). Parallel tournament top-2 epilogue; exact fp32 rerank.

#define D      64
#define K      1024
#define MTILE  256        // points per CTA
#define WTILE  256        // codewords per tile
#define KT     (K / WTILE)
#define BLOCK  512
#define HW     1024       // d-stride inside x

// ---- smem layout (bytes) ----
#define OFF_YHI 0                 // 256 x 128B fp16
#define OFF_YLO 32768
#define OFF_W   65536             // 2 buffers x (hi 32KB + lo 32KB)
#define W_BUF   65536
#define OFF_WN  196608            // 1024 fp32 norms
#define OFF_XN  200704            // 2 x 256 fp32 partial ||x||^2
#define OFF_TOP 202752            // 256 x uint2 (k1, k2)
#define OFF_IDX 204800            // 256 int
#define SMEM_TOTAL 205824

#define SW(o) ((o) ^ (((o) >> 3) & 0x70))

// ---- global scratch: swizzled fp16 codebook tiles (hi,lo) + norms ----
__device__ __align__(1024) static char  g_wsw[KT][2][WTILE * 128];
__device__ __align__(16)   static float g_wn[K];

static __device__ __forceinline__ uint32_t smem_u32(const void* p) {
    uint32_t a;
    asm("{ .reg .u64 t; cvta.to.shared.u64 t, %1; cvt.u32.u64 %0, t; }" : "=r"(a) : "l"(p));
    return a;
}
static __device__ __forceinline__ void cp16(uint32_t saddr, const void* g) {
    asm volatile("cp.async.cg.shared.global [%0], [%1], 16;"
                 :: "r"(saddr), "l"((size_t)__cvta_generic_to_global(g)) : "memory");
}
static __device__ __forceinline__ void ldsm4(uint32_t r[4], uint32_t addr) {
    asm volatile("ldmatrix.sync.aligned.m8n8.x4.shared.b16 {%0,%1,%2,%3}, [%4];"
                 : "=r"(r[0]), "=r"(r[1]), "=r"(r[2]), "=r"(r[3]) : "r"(addr));
}
static __device__ __forceinline__ void mma16816(float c[4], const uint32_t a[4],
                                                uint32_t b0, uint32_t b1) {
    asm volatile("mma.sync.aligned.m16n8k16.row.col.f32.f16.f16.f32 "
                 "{%0,%1,%2,%3}, {%4,%5,%6,%7}, {%8,%9}, {%0,%1,%2,%3};"
                 : "+f"(c[0]), "+f"(c[1]), "+f"(c[2]), "+f"(c[3])
                 : "r"(a[0]), "r"(a[1]), "r"(a[2]), "r"(a[3]), "r"(b0), "r"(b1));
}
static __device__ __forceinline__ uint32_t umn(uint32_t a, uint32_t b) { return a < b ? a : b; }
static __device__ __forceinline__ uint32_t umx(uint32_t a, uint32_t b) { return a > b ? a : b; }

// scores are >= ~1 (nonnegative floats): raw bits are order-preserving.
// 13 mantissa bits kept; codeword index in low 10 bits.
static __device__ __forceinline__ uint32_t fkey(float v, int col) {
    return (__float_as_uint(v) & 0xFFFFFC00u) | (uint32_t)col;
}
// merge two sorted pairs -> top-2 of union
static __device__ __forceinline__ void mrg2(uint32_t& o1, uint32_t& o2,
                                            uint32_t a1, uint32_t a2,
                                            uint32_t b1, uint32_t b2) {
    o1 = umn(a1, b1);
    o2 = umn(umx(a1, b1), umn(a2, b2));
}
// tournament top-2 of 8 keys (tree depth ~5)
static __device__ __forceinline__ void top2of8(const uint32_t k[8],
                                               uint32_t& t1, uint32_t& t2) {
    uint32_t a1 = umn(k[0], k[1]), a2 = umx(k[0], k[1]);
    uint32_t b1 = umn(k[2], k[3]), b2 = umx(k[2], k[3]);
    uint32_t c1 = umn(k[4], k[5]), c2 = umx(k[4], k[5]);
    uint32_t d1 = umn(k[6], k[7]), d2 = umx(k[6], k[7]);
    uint32_t e1, e2, f1, f2;
    mrg2(e1, e2, a1, a2, b1, b2);
    mrg2(f1, f2, c1, c2, d1, d2);
    mrg2(t1, t2, e1, e2, f1, f2);
}

// ---------------- pre-kernel: convert codebook once ----------------
__global__ __launch_bounds__(256)
void vq_prep_kernel(const float* __restrict__ w)
{
    const int gid = blockIdx.x * 256 + threadIdx.x;   // 128 blocks -> 32768 threads
    {
        const int i  = gid;                           // pair index
        const int kr = i >> 5;                        // codeword 0..1023
        const int p  = i & 31;                        // pair within row
        float2 v = ((const float2*)w)[i];
        __half h0 = __float2half_rn(v.x), h1 = __float2half_rn(v.y);
        __half l0 = __float2half_rn(v.x - __half2float(h0));
        __half l1 = __float2half_rn(v.y - __half2float(h1));
        const int kt = kr >> 8, pr = kr & 255;
        uint32_t o = SW((uint32_t)(pr * 128 + p * 4));
        *(__half2*)(g_wsw[kt][0] + o) = __halves2half2(h0, h1);
        *(__half2*)(g_wsw[kt][1] + o) = __halves2half2(l0, l1);
    }
    if (gid < K) {
        const float4* wr = (const float4*)(w + (size_t)gid * D);
        float s = 0.0f;
#pragma unroll
        for (int q = 0; q < D / 4; q++) {
            float4 f = wr[q];
            s = fmaf(f.x, f.x, s); s = fmaf(f.y, f.y, s);
            s = fmaf(f.z, f.z, s); s = fmaf(f.w, f.w, s);
        }
        g_wn[gid] = s;
    }
}

// ---------------- main kernel ----------------
__global__ __launch_bounds__(BLOCK, 1)
void vq_hmma_kernel(const float* __restrict__ x,
                    const float* __restrict__ w,
                    float* __restrict__ out)
{
    extern __shared__ char sm[];
    const uint32_t smb = smem_u32(sm);
    const int tid  = threadIdx.x;
    const int lane = tid & 31;
    const int warp = tid >> 5;

    const int n0   = blockIdx.x * MTILE;
    const int bimg = n0 >> 10;
    const int hw0  = n0 & (HW - 1);

    // ---- prefetch: norms + tile0 (group 0), tile1 (group 1) ----
    if (tid < 256) cp16(smb + OFF_WN + tid * 16, g_wn + tid * 4);
    {
        uint32_t dst = smb + OFF_W;                     // buf 0
        const char* src = g_wsw[0][0];
#pragma unroll
        for (int i = 0; i < 8; i++) {
            int off = (tid + i * BLOCK) * 16;
            cp16(dst + off, src + off);
        }
    }
    asm volatile("cp.async.commit_group;" ::: "memory");
    {
        uint32_t dst = smb + OFF_W + W_BUF;             // buf 1
        const char* src = g_wsw[1][0];
#pragma unroll
        for (int i = 0; i < 8; i++) {
            int off = (tid + i * BLOCK) * 16;
            cp16(dst + off, src + off);
        }
    }
    asm volatile("cp.async.commit_group;" ::: "memory");

    // ---- build Y = -2x (fp16 hi/lo, swizzled) + partial ||x||^2 ----
    {
        const int p  = tid & 255;
        const int d0 = (tid >> 8) * 32;
        const float* xp = x + (size_t)bimg * D * HW + hw0 + p;
        char* yhi = sm + OFF_YHI;
        char* ylo = sm + OFF_YLO;
        const uint32_t rb = (uint32_t)p * 128;
        float xs = 0.0f;
#pragma unroll
        for (int dd = 0; dd < 32; dd += 2) {
            const int d = d0 + dd;
            float xv0 = xp[(size_t)d * HW];
            float xv1 = xp[(size_t)(d + 1) * HW];
            xs = fmaf(xv0, xv0, xs);
            xs = fmaf(xv1, xv1, xs);
            float v0 = -2.0f * xv0, v1 = -2.0f * xv1;
            __half h0 = __float2half_rn(v0), h1 = __float2half_rn(v1);
            __half l0 = __float2half_rn(v0 - __half2float(h0));
            __half l1 = __float2half_rn(v1 - __half2float(h1));
            uint32_t o = SW(rb + (uint32_t)d * 2);
            *(__half2*)(yhi + o) = __halves2half2(h0, h1);
            *(__half2*)(ylo + o) = __halves2half2(l0, l1);
        }
        ((float*)(sm + OFF_XN))[(tid >> 8) * 256 + p] = xs;
    }
    __syncthreads();   // Y + xn partials visible

    // ---- per-lane row norms: xn + 1 (scores become ||x-w||^2 + 1 >= ~1) ----
    float xnA, xnB;
    {
        const float* xpart = (const float*)(sm + OFF_XN);
        const int r0 = warp * 16 + (lane >> 2);
        xnA = xpart[r0] + xpart[256 + r0] + 1.0f;
        xnB = xpart[r0 + 8] + xpart[256 + r0 + 8] + 1.0f;
    }

    // ---- A fragments (this warp's 16 points x 64 d), hi and lo, in regs ----
    uint32_t ahi[4][4], alo[4][4];
    const int lr = lane & 7;
    const int mI = lane >> 3;
    {
        const uint32_t arow = (uint32_t)(warp * 16 + (mI & 1) * 8 + lr) * 128;
#pragma unroll
        for (int kc = 0; kc < 4; kc++) {
            uint32_t ch = (uint32_t)((kc * 2 + (mI >> 1)) ^ lr) * 16;
            ldsm4(ahi[kc], smb + OFF_YHI + arow + ch);
            ldsm4(alo[kc], smb + OFF_YLO + arow + ch);
        }
    }

    const uint32_t offb0 = (uint32_t)lr * 128 + (uint32_t)(mI ^ lr) * 16;       // k-chunks 0-3
    const uint32_t offb1 = (uint32_t)lr * 128 + (uint32_t)((4 + mI) ^ lr) * 16; // k-chunks 4-7
    const float* wn = (const float*)(sm + OFF_WN);

    uint32_t kA1 = 0xFFFFFFFFu, kA2 = 0xFFFFFFFFu;
    uint32_t kB1 = 0xFFFFFFFFu, kB2 = 0xFFFFFFFFu;

#pragma unroll 1
    for (int kt = 0; kt < KT; kt++) {
        const int buf = kt & 1;
        if (kt < KT - 1) asm volatile("cp.async.wait_group 1;" ::: "memory");
        else             asm volatile("cp.async.wait_group 0;" ::: "memory");
        __syncthreads();   // tile visible; prior compute on buf done

        const uint32_t gbhi = smb + OFF_W + (uint32_t)buf * W_BUF;
        const uint32_t gblo = gbhi + 32768;

#pragma unroll 1
        for (int g = 0; g < WTILE / 32; g++) {
            const uint32_t th = gbhi + (uint32_t)g * 32 * 128;
            const uint32_t tl = gblo + (uint32_t)g * 32 * 128;
            const int colb = kt * WTILE + g * 32 + 2 * (lane & 3);

            float c[4][4];
#pragma unroll
            for (int nt = 0; nt < 4; nt++) {
                float2 nn = *(const float2*)(wn + colb + nt * 8);
                c[nt][0] = nn.x + xnA; c[nt][1] = nn.y + xnA;
                c[nt][2] = nn.x + xnB; c[nt][3] = nn.y + xnB;
            }

            // pass group 1: B = hi, A in {hi, lo}
#pragma unroll
            for (int kc32 = 0; kc32 < 2; kc32++) {
                const uint32_t ob = kc32 ? offb1 : offb0;
#pragma unroll
                for (int nt = 0; nt < 4; nt++) {
                    uint32_t bb[4];
                    ldsm4(bb, th + (uint32_t)nt * 1024 + ob);
                    mma16816(c[nt], ahi[kc32 * 2],     bb[0], bb[1]);
                    mma16816(c[nt], ahi[kc32 * 2 + 1], bb[2], bb[3]);
                    mma16816(c[nt], alo[kc32 * 2],     bb[0], bb[1]);
                    mma16816(c[nt], alo[kc32 * 2 + 1], bb[2], bb[3]);
                }
            }
            // pass group 2: B = lo, A = hi
#pragma unroll
            for (int kc32 = 0; kc32 < 2; kc32++) {
                const uint32_t ob = kc32 ? offb1 : offb0;
#pragma unroll
                for (int nt = 0; nt < 4; nt++) {
                    uint32_t bb[4];
                    ldsm4(bb, tl + (uint32_t)nt * 1024 + ob);
                    mma16816(c[nt], ahi[kc32 * 2],     bb[0], bb[1]);
                    mma16816(c[nt], ahi[kc32 * 2 + 1], bb[2], bb[3]);
                }
            }

            // ---- parallel tournament top-2 epilogue ----
            {
                uint32_t kA[8], kB[8];
#pragma unroll
                for (int nt = 0; nt < 4; nt++) {
                    const int c0 = colb + nt * 8;
                    kA[2*nt]   = fkey(c[nt][0], c0);
                    kA[2*nt+1] = fkey(c[nt][1], c0 + 1);
                    kB[2*nt]   = fkey(c[nt][2], c0);
                    kB[2*nt+1] = fkey(c[nt][3], c0 + 1);
                }
                uint32_t t1, t2;
                top2of8(kA, t1, t2);
                {
                    uint32_t n1 = umn(kA1, t1);
                    uint32_t n2 = umn(umx(kA1, t1), umn(kA2, t2));
                    kA1 = n1; kA2 = n2;
                }
                top2of8(kB, t1, t2);
                {
                    uint32_t n1 = umn(kB1, t1);
                    uint32_t n2 = umn(umx(kB1, t1), umn(kB2, t2));
                    kB1 = n1; kB2 = n2;
                }
            }
        }
        __syncthreads();   // compute on buf done -> safe to overwrite
        if (kt + 2 < KT) {
            uint32_t dst = smb + OFF_W + (uint32_t)buf * W_BUF;
            const char* src = g_wsw[kt + 2][0];
#pragma unroll
            for (int i = 0; i < 8; i++) {
                int off = (tid + i * BLOCK) * 16;
                cp16(dst + off, src + off);
            }
            asm volatile("cp.async.commit_group;" ::: "memory");
        }
    }

    // ---- merge top-2 across the 4 lanes sharing each row ----
#pragma unroll
    for (int mm = 1; mm <= 2; mm <<= 1) {
        uint32_t o1, o2, mn;
        o1 = __shfl_xor_sync(0xFFFFFFFFu, kA1, mm);
        o2 = __shfl_xor_sync(0xFFFFFFFFu, kA2, mm);
        mn = umn(kA1, o1); kA2 = umn(umn(kA2, o2), umx(kA1, o1)); kA1 = mn;
        o1 = __shfl_xor_sync(0xFFFFFFFFu, kB1, mm);
        o2 = __shfl_xor_sync(0xFFFFFFFFu, kB2, mm);
        mn = umn(kB1, o1); kB2 = umn(umn(kB2, o2), umx(kB1, o1)); kB1 = mn;
    }
    if ((lane & 3) == 0) {
        uint2* top = (uint2*)(sm + OFF_TOP);
        const int pA = warp * 16 + (lane >> 2);
        top[pA]     = make_uint2(kA1, kA2);
        top[pA + 8] = make_uint2(kB1, kB2);
    }
    __syncthreads();

    // ---- exact fp32 rerank of the two candidates (always) ----
    int* sidx = (int*)(sm + OFF_IDX);
    if (tid < MTILE) {
        uint2 t = ((const uint2*)(sm + OFF_TOP))[tid];
        int i1 = (int)(t.x & 1023u), i2 = (int)(t.y & 1023u);
        int fi = i1;
        if (i2 != i1) {
            const float* xr = x + (size_t)bimg * D * HW + hw0 + tid;
            const float* w1 = w + (size_t)i1 * D;
            const float* w2 = w + (size_t)i2 * D;
            float s1 = 0.0f, s2 = 0.0f;
#pragma unroll 8
            for (int d = 0; d < D; d++) {
                float xv = xr[(size_t)d * HW];
                float a = w1[d], cc = w2[d];
                s1 = fmaf(a,  fmaf(-2.0f, xv, a),  s1);
                s2 = fmaf(cc, fmaf(-2.0f, xv, cc), s2);
            }
            if (s2 < s1 || (s2 == s1 && i2 < i1)) fi = i2;
        }
        sidx[tid] = fi;
    }
    __syncthreads();

    // ---- coalesced gather of winning codewords ----
    {
        const float4* w4 = (const float4*)w;
        float4* o4 = (float4*)out;
        const size_t obase = (size_t)blockIdx.x * MTILE * (D / 4);
#pragma unroll 4
        for (int i = tid; i < MTILE * (D / 4); i += BLOCK) {
            const int p = i >> 4, d4 = i & 15;
            o4[obase + i] = w4[(size_t)sidx[p] * (D / 4) + d4];
        }
    }
}

extern "C" void kernel_launch(void* const* d_in, const int* in_sizes, int n_in,
                              void* d_out, int out_size)
{
    const float* x = (const float*)d_in[0];   // [64, 64, 32, 32]
    const float* w = (const float*)d_in[1];   // [1024, 64]
    float* out = (float*)d_out;               // [65536, 64]
    (void)in_sizes; (void)n_in; (void)out_size;

    vq_prep_kernel<<<128, 256>>>(w);
    cudaFuncSetAttribute(vq_hmma_kernel, cudaFuncAttributeMaxDynamicSharedMemorySize, SMEM_TOTAL);
    vq_hmma_kernel<<<65536 / MTILE, BLOCK, SMEM_TOTAL>>>(x, w, out);
}